// round 15
// baseline (speedup 1.0000x reference)
#include <cuda_runtime.h>
#include <cuda_bf16.h>

// BoxFilter: out[b,c,i,j] = sum of x over rows [max(0,i-R), min(H-1,i+R)]
//                                        cols [max(0,j-R), min(W-1,j+R)]
// (identity of diff_y(cumsum(diff_x(cumsum(x,H),r),W),r) with truncated edges)
//
// Single pass. Horizontal 9-tap via 3 aligned LDG.128 + sliding window.
// Vertical running sum with a per-thread smem ring (depth 8; 2R==8 so the
// subtract slot equals the add slot -> read-before-write). No __syncthreads.
// Body unrolled x2 with all 6 LDG.128 front-batched to double per-warp MLP.

#define R 4
#define NT 160                 // threads per block (5 warps)
#define MINB 6                 // regs capped at 68 -> room for 6-deep load batch
#define CPT 4                  // columns per thread (float4)
#define TW (NT * CPT)          // 640 cols per block tile -> 1920/640 = 3 exact
#define ZCHUNKS 12             // 3*24*12 = 864 blocks <= 148*6 -> single wave
#define RING 8                 // == 2R

__device__ __forceinline__ float4 hbox_fast(const float* __restrict__ rowp, int c) {
    const float4* p = reinterpret_cast<const float4*>(rowp + (c - R));
    float4 a = p[0], b = p[1], d = p[2];
    float h0 = ((a.x + a.y) + (a.z + a.w)) + ((b.x + b.y) + (b.z + b.w)) + d.x;
    float h1 = h0 - a.x + d.y;
    float h2 = h1 - a.y + d.z;
    float h3 = h2 - a.z + d.w;
    return make_float4(h0, h1, h2, h3);
}

__device__ __forceinline__ float4 hbox_slow(const float* __restrict__ rowp, int c, int W) {
    float s[2 * R + CPT];
#pragma unroll
    for (int k = 0; k < 2 * R + CPT; ++k) {
        int cc = c - R + k;
        s[k] = (cc >= 0 && cc < W) ? rowp[cc] : 0.0f;
    }
    float h0 = 0.0f;
#pragma unroll
    for (int k = 0; k < 2 * R + 1; ++k) h0 += s[k];
    float h1 = h0 - s[0] + s[2 * R + 1];
    float h2 = h1 - s[1] + s[2 * R + 2];
    float h3 = h2 - s[2] + s[2 * R + 3];
    return make_float4(h0, h1, h2, h3);
}

__global__ __launch_bounds__(NT, MINB) void box_kernel(
    const float* __restrict__ x, float* __restrict__ out,
    int H, int W, int rows_per_chunk)
{
    __shared__ float4 ring[RING][NT];   // 20.5 KB; per-thread private slots

    const int t = threadIdx.x;
    const int c = blockIdx.x * TW + t * CPT;
    if (c >= W) return;
    const bool fast = (c >= R) && (c + CPT - 1 + R < W);

    const size_t img_off = (size_t)blockIdx.y * (size_t)H * (size_t)W;
    const float* img = x + img_off;
    float* oimg = out + img_off;

    const int y0 = blockIdx.z * rows_per_chunk;
    if (y0 >= H) return;
    const int y1 = min(H, y0 + rows_per_chunk);

    // Prime: vsum = sum h(rows max(0,y0-R) .. y0+R-1); stash each h in the ring.
    float4 vsum = make_float4(0.0f, 0.0f, 0.0f, 0.0f);
    for (int row = max(0, y0 - R); row < y0 + R && row < H; ++row) {
        const float* rowp = img + (size_t)row * W;
        float4 h = fast ? hbox_fast(rowp, c) : hbox_slow(rowp, c, W);
        ring[row & (RING - 1)][t] = h;
        vsum.x += h.x; vsum.y += h.y; vsum.z += h.z; vsum.w += h.w;
    }

    const int body_lo = min(y1, max(y0, R));           // first i with i-R >= 0
    const int body_hi = max(body_lo, min(y1, H - R));  // last+1 i with i+R < H

    // --- head: i < R, add only ---
    for (int i = y0; i < body_lo; ++i) {
        const int ra = i + R;
        const float* rowp = img + (size_t)ra * W;
        float4 h = fast ? hbox_fast(rowp, c) : hbox_slow(rowp, c, W);
        ring[ra & (RING - 1)][t] = h;
        vsum.x += h.x; vsum.y += h.y; vsum.z += h.z; vsum.w += h.w;
        *reinterpret_cast<float4*>(oimg + (size_t)i * W + c) = vsum;
    }

    // --- body: interior, unrolled x2, 6 LDG.128 + 2 LDS.128 front-batched ---
    if (fast) {
        int i = body_lo;
        for (; i + 1 < body_hi; i += 2) {
            const int slot0 = (i + R) & (RING - 1);
            const int slot1 = (i + 1 + R) & (RING - 1);
            const float4* pa = reinterpret_cast<const float4*>(
                img + (size_t)(i + R) * W + (c - R));
            const float4* pb = reinterpret_cast<const float4*>(
                img + (size_t)(i + 1 + R) * W + (c - R));
            // front-batch: 6 independent global loads + 2 shared loads
            float4 a0 = pa[0], a1 = pa[1], a2 = pa[2];
            float4 b0 = pb[0], b1 = pb[1], b2 = pb[2];
            float4 g0 = ring[slot0][t];                 // h(i-R)
            float4 g1 = ring[slot1][t];                 // h(i+1-R)

            float p0 = ((a0.x + a0.y) + (a0.z + a0.w)) + ((a1.x + a1.y) + (a1.z + a1.w)) + a2.x;
            float p1 = p0 - a0.x + a2.y;
            float p2 = p1 - a0.y + a2.z;
            float p3 = p2 - a0.z + a2.w;

            float q0 = ((b0.x + b0.y) + (b0.z + b0.w)) + ((b1.x + b1.y) + (b1.z + b1.w)) + b2.x;
            float q1 = q0 - b0.x + b2.y;
            float q2 = q1 - b0.y + b2.z;
            float q3 = q2 - b0.z + b2.w;

            ring[slot0][t] = make_float4(p0, p1, p2, p3);
            ring[slot1][t] = make_float4(q0, q1, q2, q3);

            vsum.x += p0; vsum.y += p1; vsum.z += p2; vsum.w += p3;
            *reinterpret_cast<float4*>(oimg + (size_t)i * W + c) = vsum;
            vsum.x += q0 - g0.x; vsum.y += q1 - g0.y;
            vsum.z += q2 - g0.z; vsum.w += q3 - g0.w;
            *reinterpret_cast<float4*>(oimg + (size_t)(i + 1) * W + c) = vsum;
            vsum.x -= g1.x; vsum.y -= g1.y; vsum.z -= g1.z; vsum.w -= g1.w;
        }
        for (; i < body_hi; ++i) {
            const int slot = (i + R) & (RING - 1);
            float4 g = ring[slot][t];
            const float4* pa = reinterpret_cast<const float4*>(
                img + (size_t)(i + R) * W + (c - R));
            float4 a0 = pa[0], a1 = pa[1], a2 = pa[2];

            float h0 = ((a0.x + a0.y) + (a0.z + a0.w)) + ((a1.x + a1.y) + (a1.z + a1.w)) + a2.x;
            float h1 = h0 - a0.x + a2.y;
            float h2 = h1 - a0.y + a2.z;
            float h3 = h2 - a0.z + a2.w;

            ring[slot][t] = make_float4(h0, h1, h2, h3);
            vsum.x += h0; vsum.y += h1; vsum.z += h2; vsum.w += h3;
            *reinterpret_cast<float4*>(oimg + (size_t)i * W + c) = vsum;
            vsum.x -= g.x; vsum.y -= g.y; vsum.z -= g.z; vsum.w -= g.w;
        }
    } else {
        for (int i = body_lo; i < body_hi; ++i) {
            const int slot = (i + R) & (RING - 1);
            float4 g = ring[slot][t];
            float4 h = hbox_slow(img + (size_t)(i + R) * W, c, W);
            ring[slot][t] = h;
            vsum.x += h.x; vsum.y += h.y; vsum.z += h.z; vsum.w += h.w;
            *reinterpret_cast<float4*>(oimg + (size_t)i * W + c) = vsum;
            vsum.x -= g.x; vsum.y -= g.y; vsum.z -= g.z; vsum.w -= g.w;
        }
    }

    // --- tail: i + R >= H, subtract only ---
    for (int i = body_hi; i < y1; ++i) {
        const int ra = i + R;
        if (ra < H) {
            const float* rowp = img + (size_t)ra * W;
            float4 h = fast ? hbox_fast(rowp, c) : hbox_slow(rowp, c, W);
            ring[ra & (RING - 1)][t] = h;
            vsum.x += h.x; vsum.y += h.y; vsum.z += h.z; vsum.w += h.w;
        }
        *reinterpret_cast<float4*>(oimg + (size_t)i * W + c) = vsum;
        if (i - R >= 0) {
            float4 g = ring[(i - R) & (RING - 1)][t];
            vsum.x -= g.x; vsum.y -= g.y; vsum.z -= g.z; vsum.w -= g.w;
        }
    }
}

extern "C" void kernel_launch(void* const* d_in, const int* in_sizes, int n_in,
                              void* d_out, int out_size) {
    const float* x = (const float*)d_in[0];
    float* out = (float*)d_out;

    const int H = 1080;
    const int W = 1920;
    const int BC = out_size / (H * W);   // 24 (B*C)

    const int rows_per_chunk = (H + ZCHUNKS - 1) / ZCHUNKS;  // 90
    dim3 grid((W + TW - 1) / TW, BC, ZCHUNKS);               // 3 x 24 x 12 = 864 blocks
    box_kernel<<<grid, NT>>>(x, out, H, W, rows_per_chunk);
}